// round 3
// baseline (speedup 1.0000x reference)
#include <cuda_runtime.h>
#include <cstdint>

#define DIM   128
#define MAX_N 50000
#define MAX_E 800000
#define KT    32     // k-tile for GEMM
#define RPB   64     // rows per block for GEMM
#define SCAN_T 1024

// ---------------------------------------------------------------------------
// Scratch (no allocations allowed). 16B-aligned for float4 access.
// ---------------------------------------------------------------------------
__device__ __align__(16) float g_aggr[MAX_N * DIM];   // scaled mean aggregation
__device__ __align__(16) float g_h[MAX_N * DIM];      // layer-1 output
__device__ int   g_deg[MAX_N];
__device__ int   g_row[MAX_N];          // CSR row starts
__device__ int   g_cursor[MAX_N];
__device__ int   g_csr[MAX_E];          // CSR: src per (grouped-by-tgt) edge

// ---------------------------------------------------------------------------
// CSR construction
// ---------------------------------------------------------------------------
__global__ void zero_counts_kernel(int n_nodes) {
    int i = blockIdx.x * blockDim.x + threadIdx.x;
    if (i < n_nodes) { g_deg[i] = 0; g_cursor[i] = 0; }
}

__global__ void degree_kernel(const int* __restrict__ tgt, int E, int n_nodes) {
    int e = blockIdx.x * blockDim.x + threadIdx.x;
    if (e < E) {
        int d = tgt[e];
        if ((unsigned)d < (unsigned)n_nodes) atomicAdd(&g_deg[d], 1);
    }
}

// Single-block exclusive scan of g_deg -> g_row (n_nodes <= 50176)
__global__ void __launch_bounds__(SCAN_T)
scan_kernel(int n_nodes) {
    __shared__ int partial[SCAN_T];
    const int t = threadIdx.x;
    const int C = (n_nodes + SCAN_T - 1) / SCAN_T;
    const int start = t * C;
    const int end   = min(start + C, n_nodes);

    int s = 0;
    for (int i = start; i < end; i++) s += g_deg[i];
    partial[t] = s;
    __syncthreads();

    for (int off = 1; off < SCAN_T; off <<= 1) {
        int v = 0;
        if (t >= off) v = partial[t - off];
        __syncthreads();
        if (t >= off) partial[t] += v;
        __syncthreads();
    }

    int excl = (t == 0) ? 0 : partial[t - 1];
    for (int i = start; i < end; i++) {
        g_row[i] = excl;
        excl += g_deg[i];
    }
}

__global__ void fill_kernel(const int* __restrict__ src,
                            const int* __restrict__ tgt, int E, int n_nodes) {
    int e = blockIdx.x * blockDim.x + threadIdx.x;
    if (e < E) {
        int d = tgt[e];
        int s = src[e];
        if ((unsigned)d < (unsigned)n_nodes && (unsigned)s < (unsigned)n_nodes) {
            int pos = atomicAdd(&g_cursor[d], 1);
            g_csr[g_row[d] + pos] = s;
        }
    }
}

// ---------------------------------------------------------------------------
// Aggregation: one warp per node. Lane l owns floats [4l, 4l+4).
// Batch <=32 neighbor ids per lane-load, broadcast via shfl; each step is an
// independent LDG.128 -> high MLP, L2-resident gathers.
// Writes the 1/deg-scaled mean directly.
// ---------------------------------------------------------------------------
__global__ void aggregate_kernel(const float* __restrict__ xin,
                                 int use_h, int n_nodes) {
    int warp = (blockIdx.x * blockDim.x + threadIdx.x) >> 5;
    int lane = threadIdx.x & 31;
    if (warp >= n_nodes) return;

    const float* __restrict__ X = use_h ? g_h : xin;
    const int base = g_row[warp];
    const int deg  = g_deg[warp];

    float ax = 0.f, ay = 0.f, az = 0.f, aw = 0.f;
    for (int i0 = 0; i0 < deg; i0 += 32) {
        int sv = 0;
        if (i0 + lane < deg) sv = g_csr[base + i0 + lane];
        int m = min(32, deg - i0);
        for (int j = 0; j < m; j++) {
            int s = __shfl_sync(0xffffffffu, sv, j);
            float4 v = *reinterpret_cast<const float4*>(
                X + (size_t)s * DIM + lane * 4);
            ax += v.x; ay += v.y; az += v.z; aw += v.w;
        }
    }
    float inv = 1.0f / fmaxf((float)deg, 1.0f);
    float4 o = make_float4(ax * inv, ay * inv, az * inv, aw * inv);
    *reinterpret_cast<float4*>(g_aggr + (size_t)warp * DIM + lane * 4) = o;
}

// ---------------------------------------------------------------------------
// Fused GEMM + bias + relu:
//   out[n,j] = relu( sum_k X[n,k]*W[k,j] + sum_k aggr[n,k]*W[128+k,j] + b[j] )
// 256 threads = (32 tx, 8 ty); block tile 64x128; thread tile 8x4.
// ---------------------------------------------------------------------------
__global__ void __launch_bounds__(256)
gemm_relu_kernel(const float* __restrict__ Xin,
                 const float* __restrict__ W,   // [256,128] row-major
                 const float* __restrict__ b,   // [128]
                 float* __restrict__ outp,
                 int use_h_in, int out_is_h, int n_nodes) {
    __shared__ float in_s[RPB][KT];   // 64 x 32
    __shared__ float w_s[KT][DIM];    // 32 x 128
    __shared__ float b_s[DIM];

    const float* __restrict__ X = use_h_in ? g_h : Xin;
    float* __restrict__ out = out_is_h ? g_h : outp;

    const int row0 = blockIdx.x * RPB;
    const int tid  = threadIdx.x;
    const int tx   = tid & 31;
    const int ty   = tid >> 5;

    if (tid >= 128) b_s[tid - 128] = b[tid - 128];

    float acc[8][4];
#pragma unroll
    for (int i = 0; i < 8; i++)
#pragma unroll
        for (int c = 0; c < 4; c++) acc[i][c] = 0.0f;

    for (int kt = 0; kt < 2 * DIM; kt += KT) {
        __syncthreads();
        // W tile: 32x128 floats = 1024 float4, 4 per thread
        {
            const float4* Wv = reinterpret_cast<const float4*>(W + (size_t)kt * DIM);
            float4* wsv = reinterpret_cast<float4*>(&w_s[0][0]);
#pragma unroll
            for (int i = 0; i < 4; i++)
                wsv[tid + 256 * i] = Wv[tid + 256 * i];
        }
        // Input tile: 64x32 floats = 512 float4, 2 per thread
        {
            const bool agg = (kt >= DIM);
            const int kbase = agg ? (kt - DIM) : kt;
            const float* __restrict__ srcp = agg ? g_aggr : X;
#pragma unroll
            for (int i = 0; i < 2; i++) {
                int idx = tid + 256 * i;   // float4 index (8 per row)
                int r = idx >> 3;
                int c4 = idx & 7;
                int gr = row0 + r;
                float4 v = make_float4(0.f, 0.f, 0.f, 0.f);
                if (gr < n_nodes)
                    v = reinterpret_cast<const float4*>(
                            srcp + (size_t)gr * DIM + kbase)[c4];
                *reinterpret_cast<float4*>(&in_s[r][c4 * 4]) = v;
            }
        }
        __syncthreads();
#pragma unroll
        for (int kk = 0; kk < KT; kk++) {
            float w0 = w_s[kk][tx];
            float w1 = w_s[kk][tx + 32];
            float w2 = w_s[kk][tx + 64];
            float w3 = w_s[kk][tx + 96];
#pragma unroll
            for (int i = 0; i < 8; i++) {
                float a = in_s[ty * 8 + i][kk];
                acc[i][0] = fmaf(a, w0, acc[i][0]);
                acc[i][1] = fmaf(a, w1, acc[i][1]);
                acc[i][2] = fmaf(a, w2, acc[i][2]);
                acc[i][3] = fmaf(a, w3, acc[i][3]);
            }
        }
    }

#pragma unroll
    for (int i = 0; i < 8; i++) {
        int gr = row0 + ty * 8 + i;
        if (gr < n_nodes) {
#pragma unroll
            for (int c = 0; c < 4; c++) {
                int j = tx + 32 * c;
                out[(size_t)gr * DIM + j] = fmaxf(acc[i][c] + b_s[j], 0.0f);
            }
        }
    }
}

// ---------------------------------------------------------------------------
// Launch
// ---------------------------------------------------------------------------
extern "C" void kernel_launch(void* const* d_in, const int* in_sizes, int n_in,
                              void* d_out, int out_size) {
    const float* x  = (const float*)d_in[0];
    const int*   ei = (const int*)d_in[1];   // JAX x64 disabled -> int32
    const float* W1 = (const float*)d_in[2];
    const float* b1 = (const float*)d_in[3];
    const float* W2 = (const float*)d_in[4];
    const float* b2 = (const float*)d_in[5];
    float* out = (float*)d_out;

    const int n_nodes = in_sizes[0] / DIM;   // 50000
    const int E       = in_sizes[1] / 2;     // 800000
    const int* src = ei;
    const int* tgt = ei + E;

    const int threads = 256;
    const int nb = (n_nodes + threads - 1) / threads;
    const int eb = (E + threads - 1) / threads;
    const int ab = ((n_nodes * 32) + threads - 1) / threads;
    const int gb = (n_nodes + RPB - 1) / RPB;

    // CSR build (shared by both layers)
    zero_counts_kernel<<<nb, threads>>>(n_nodes);
    degree_kernel<<<eb, threads>>>(tgt, E, n_nodes);
    scan_kernel<<<1, SCAN_T>>>(n_nodes);
    fill_kernel<<<eb, threads>>>(src, tgt, E, n_nodes);

    // layer 1: aggr(x) -> gemm -> g_h
    aggregate_kernel<<<ab, threads>>>(x, /*use_h=*/0, n_nodes);
    gemm_relu_kernel<<<gb, threads>>>(x, W1, b1, out,
                                      /*use_h_in=*/0, /*out_is_h=*/1, n_nodes);

    // layer 2: aggr(g_h) -> gemm -> out
    aggregate_kernel<<<ab, threads>>>(x, /*use_h=*/1, n_nodes);
    gemm_relu_kernel<<<gb, threads>>>(x, W2, b2, out,
                                      /*use_h_in=*/1, /*out_is_h=*/0, n_nodes);
}